// round 1
// baseline (speedup 1.0000x reference)
#include <cuda_runtime.h>
#include <cuda_bf16.h>
#include <cstdint>

// Problem constants (fixed by the reference).
constexpr int B = 8, C = 3, H = 720, W = 1280;
constexpr int HW = H * W;            // 921600
constexpr int NPIX = B * HW;         // 7372800
constexpr int CHW = C * HW;          // per-batch channel stride block

__global__ __launch_bounds__(256)
void forward_warp_kernel(const float* __restrict__ im0,
                         const float2* __restrict__ flow,
                         float* __restrict__ out) {
    int p = blockIdx.x * blockDim.x + threadIdx.x;
    if (p >= NPIX) return;

    int b = p / HW;
    int r = p - b * HW;        // h*W + w within the image
    int h = r / W;
    int w = r - h * W;

    float2 f = flow[p];
    float x = (float)w + f.x;
    float y = (float)h + f.y;

    float x0f = floorf(x);
    float y0f = floorf(y);
    float wx1 = x - x0f;
    float wx0 = 1.0f - wx1;
    float wy1 = y - y0f;
    float wy0 = 1.0f - wy1;

    // Source pixel values for the 3 channels (coalesced along w).
    int ibase = b * CHW + r;
    float v0 = im0[ibase];
    float v1 = im0[ibase + HW];
    float v2 = im0[ibase + 2 * HW];

    float* ob = out + b * CHW;

    // 4 corners: (x0,y0) (x0+1,y0) (x0,y0+1) (x0+1,y0+1)
    #pragma unroll
    for (int cy = 0; cy < 2; ++cy) {
        float yc = y0f + (float)cy;
        if (yc < 0.0f || yc > (float)(H - 1)) continue;
        int yi = (int)yc;
        float wy = cy ? wy1 : wy0;
        #pragma unroll
        for (int cx = 0; cx < 2; ++cx) {
            float xc = x0f + (float)cx;
            if (xc < 0.0f || xc > (float)(W - 1)) continue;
            int xi = (int)xc;
            float wt = wy * (cx ? wx1 : wx0);
            int idx = yi * W + xi;
            atomicAdd(ob + idx,          wt * v0);
            atomicAdd(ob + idx + HW,     wt * v1);
            atomicAdd(ob + idx + 2 * HW, wt * v2);
        }
    }
}

extern "C" void kernel_launch(void* const* d_in, const int* in_sizes, int n_in,
                              void* d_out, int out_size) {
    const float*  im0  = (const float*)d_in[0];
    const float2* flow = (const float2*)d_in[1];
    float* out = (float*)d_out;

    // Output is poisoned; scatter-add needs a zeroed accumulator.
    cudaMemsetAsync(d_out, 0, (size_t)out_size * sizeof(float));

    int threads = 256;
    int blocks = (NPIX + threads - 1) / threads;
    forward_warp_kernel<<<blocks, threads>>>(im0, flow, out);
}